// round 3
// baseline (speedup 1.0000x reference)
#include <cuda_runtime.h>

// Bilinear_3882650435896: conv_transpose2d(x, w, stride=2) with block-diagonal
// w (per-channel bilinear filter) == depthwise 2x upsample.
// x: (4,256,128,128) f32 -> out: (4,256,258,258) f32.
//
// R2 -> R3: vectorize. One warp per output row pair (2r, 2r+1). Each lane
// loads 4 input cols per row via LDG.128; the left-neighbor tap comes from
// shfl.up (no misaligned second load stream). Each lane writes 8 output cols
// per row: 2x STG.128 on row 2r (16B-aligned), 4x STG.64 on row 2r+1 (row
// stride 1032B is only 8B-aligned). Lane 31 emits the 2-col tail for free.

#define C     256
#define HIN   128
#define HOUT  258

__global__ void __launch_bounds__(256)
bilinear_up_kernel(const float* __restrict__ x,
                   const float* __restrict__ w,
                   float* __restrict__ out)
{
    const int nc = blockIdx.y;            // n*C + c, 0..1023
    const int c  = nc & (C - 1);

    __shared__ float fs[16];
    if (threadIdx.x < 16)
        fs[threadIdx.x] = w[(size_t)c * (C + 1) * 16 + threadIdx.x];
    __syncthreads();

    const float f0 = fs[0],  f1 = fs[1],  f2 = fs[2],  f3 = fs[3];
    const float f4 = fs[4],  f5 = fs[5],  f6 = fs[6],  f7 = fs[7];
    const float f8 = fs[8],  f9 = fs[9],  f10 = fs[10], f11 = fs[11];
    const float f12 = fs[12], f13 = fs[13], f14 = fs[14], f15 = fs[15];

    const int warp = threadIdx.x >> 5;
    const int lane = threadIdx.x & 31;
    const int r    = blockIdx.x * 8 + warp;   // row-pair index, 0..128
    if (r > HIN) return;

    const float* __restrict__ xin = x + (size_t)nc * (HIN * HIN);
    const bool rm = (r >= 1);
    const bool rv = (r < HIN);

    // One LDG.128 per input row per lane: cols 4*lane .. 4*lane+3.
    float4 a0 = make_float4(0.f, 0.f, 0.f, 0.f);
    float4 a1 = make_float4(0.f, 0.f, 0.f, 0.f);
    if (rm) a0 = __ldg(reinterpret_cast<const float4*>(xin + (size_t)(r - 1) * HIN) + lane);
    if (rv) a1 = __ldg(reinterpret_cast<const float4*>(xin + (size_t)r * HIN) + lane);

    // Left neighbor (col 4*lane - 1) from lane-1's .w component.
    float p0 = __shfl_up_sync(0xffffffffu, a0.w, 1);
    float p1 = __shfl_up_sync(0xffffffffu, a1.w, 1);
    if (lane == 0) { p0 = 0.f; p1 = 0.f; }

    const float e0[5] = { p0, a0.x, a0.y, a0.z, a0.w };
    const float e1[5] = { p1, a1.x, a1.y, a1.z, a1.w };

    float r0[8], r1[8];
#pragma unroll
    for (int j = 0; j < 4; j++) {
        const float x00 = e0[j], x01 = e0[j + 1];
        const float x10 = e1[j], x11 = e1[j + 1];
        r0[2 * j]     = x11 * f0 + x10 * f2  + x01 * f8  + x00 * f10;
        r0[2 * j + 1] = x11 * f1 + x10 * f3  + x01 * f9  + x00 * f11;
        r1[2 * j]     = x11 * f4 + x10 * f6  + x01 * f12 + x00 * f14;
        r1[2 * j + 1] = x11 * f5 + x10 * f7  + x01 * f13 + x00 * f15;
    }

    float* __restrict__ o0 =
        out + (size_t)nc * (HOUT * HOUT) + (size_t)(2 * r) * HOUT + 8 * lane;
    float* __restrict__ o1 = o0 + HOUT;

    // Row 2r: base offset = nc*266256B + r*2064B + 32*lane B -> 16B aligned.
    __stcs(reinterpret_cast<float4*>(o0),     make_float4(r0[0], r0[1], r0[2], r0[3]));
    __stcs(reinterpret_cast<float4*>(o0 + 4), make_float4(r0[4], r0[5], r0[6], r0[7]));
    // Row 2r+1: +1032B -> only 8B aligned; use float2.
    __stcs(reinterpret_cast<float2*>(o1),     make_float2(r1[0], r1[1]));
    __stcs(reinterpret_cast<float2*>(o1 + 2), make_float2(r1[2], r1[3]));
    __stcs(reinterpret_cast<float2*>(o1 + 4), make_float2(r1[4], r1[5]));
    __stcs(reinterpret_cast<float2*>(o1 + 6), make_float2(r1[6], r1[7]));

    // Tail: output cols 256,257 depend only on input col 127 = lane31's .w.
    if (lane == 31) {
        const float x00 = a0.w, x10 = a1.w;   // already 0 if row invalid
        float* __restrict__ t0 = o0 - 8 * 31 + 2 * HIN;  // col 256 of row 2r
        __stcs(reinterpret_cast<float2*>(t0),
               make_float2(x10 * f2 + x00 * f10, x10 * f3 + x00 * f11));
        __stcs(reinterpret_cast<float2*>(t0 + HOUT),
               make_float2(x10 * f6 + x00 * f14, x10 * f7 + x00 * f15));
    }
}

extern "C" void kernel_launch(void* const* d_in, const int* in_sizes, int n_in,
                              void* d_out, int out_size)
{
    const float* x = (const float*)d_in[0];   // (4,256,128,128)
    const float* w = (const float*)d_in[1];   // (256,256,4,4)
    float* out = (float*)d_out;               // (4,256,258,258)

    dim3 block(256);
    dim3 grid((HIN + 1 + 7) / 8, 4 * C);      // (17, 1024)
    bilinear_up_kernel<<<grid, block>>>(x, w, out);
}

// round 4
// speedup vs baseline: 1.4012x; 1.4012x over previous
#include <cuda_runtime.h>

// Bilinear_3882650435896: conv_transpose2d(x, w, stride=2) with block-diagonal
// w (per-channel bilinear filter) == depthwise 2x upsample.
// x: (4,256,128,128) f32 -> out: (4,256,258,258) f32.
//
// R4: smem-tiled. Block = 8 warps = 8 output row pairs of one plane.
// Stage input rows R-1..R+7 in smem (float4 coalesced, zero-padded), then
// R2's proven mapping: warp w -> row pair r=R+w, lane sweeps s=lane+32k,
// float2 stores (lane stride 8B -> 256B contiguous warp requests).

#define C     256
#define HIN   128
#define HOUT  258
#define NROWS 9          // input rows staged per block
#define SROW  136        // smem row stride in words (4 left-pad + 128 + 4)

__global__ void __launch_bounds__(256)
bilinear_up_kernel(const float* __restrict__ x,
                   const float* __restrict__ w,
                   float* __restrict__ out)
{
    const int nc = blockIdx.y;            // n*C + c
    const int c  = nc & (C - 1);
    const int R  = blockIdx.x * 8;        // first row-pair index of this block

    __shared__ float fs[16];
    __shared__ float tile[NROWS * SROW];  // 1224 words = 4.9 KB

    if (threadIdx.x < 16)
        fs[threadIdx.x] = w[(size_t)c * (C + 1) * 16 + threadIdx.x];
    // Zero the 4-word left pad of every row (only word 3 is ever read,
    // but zero all 4 for simplicity). 9*4 = 36 words.
    if (threadIdx.x < NROWS * 4) {
        const int row = threadIdx.x >> 2;
        tile[row * SROW + (threadIdx.x & 3)] = 0.f;
    }

    // Stage 9 input rows as float4: 9*32 = 288 vectors, 256 threads.
    const float4* __restrict__ x4 =
        reinterpret_cast<const float4*>(x + (size_t)nc * (HIN * HIN));
    const float4 z4 = make_float4(0.f, 0.f, 0.f, 0.f);
#pragma unroll
    for (int i = threadIdx.x; i < NROWS * 32; i += 256) {
        const int row = i >> 5;           // 0..8
        const int j   = i & 31;           // float4 index within row
        const int g   = R - 1 + row;      // global input row
        const float4 v = (g >= 0 && g < HIN) ? __ldg(&x4[g * 32 + j]) : z4;
        *reinterpret_cast<float4*>(&tile[row * SROW + 4 + 4 * j]) = v;
    }
    __syncthreads();

    const float f0 = fs[0],  f1 = fs[1],  f2 = fs[2],  f3 = fs[3];
    const float f4 = fs[4],  f5 = fs[5],  f6 = fs[6],  f7 = fs[7];
    const float f8 = fs[8],  f9 = fs[9],  f10 = fs[10], f11 = fs[11];
    const float f12 = fs[12], f13 = fs[13], f14 = fs[14], f15 = fs[15];

    const int warp = threadIdx.x >> 5;
    const int lane = threadIdx.x & 31;
    const int r    = R + warp;            // row-pair index, valid if <= 128
    if (r > HIN) return;

    const float* __restrict__ sm0 = &tile[warp * SROW];        // input row r-1
    const float* __restrict__ sm1 = &tile[(warp + 1) * SROW];  // input row r

    float* __restrict__ o0 =
        out + (size_t)nc * (HOUT * HOUT) + (size_t)(2 * r) * HOUT;
    float* __restrict__ o1 = o0 + HOUT;

#pragma unroll
    for (int k = 0; k < 4; k++) {
        const int s = lane + 32 * k;
        // x[row][s-1] = tile[.][s+3], x[row][s] = tile[.][s+4] (unit lane
        // stride -> conflict-free LDS; pad makes s=0 read zero).
        const float x00 = sm0[s + 3], x01 = sm0[s + 4];
        const float x10 = sm1[s + 3], x11 = sm1[s + 4];
        const float v00 = x11 * f0 + x10 * f2  + x01 * f8  + x00 * f10;
        const float v01 = x11 * f1 + x10 * f3  + x01 * f9  + x00 * f11;
        const float v10 = x11 * f4 + x10 * f6  + x01 * f12 + x00 * f14;
        const float v11 = x11 * f5 + x10 * f7  + x01 * f13 + x00 * f15;
        __stcs(reinterpret_cast<float2*>(o0 + 2 * s), make_float2(v00, v01));
        __stcs(reinterpret_cast<float2*>(o1 + 2 * s), make_float2(v10, v11));
    }

    // Tail (output cols 256,257): only input col 127 contributes.
    if (lane == 31) {
        const float x00 = sm0[131], x10 = sm1[131];
        __stcs(reinterpret_cast<float2*>(o0 + 2 * HIN),
               make_float2(x10 * f2 + x00 * f10, x10 * f3 + x00 * f11));
        __stcs(reinterpret_cast<float2*>(o1 + 2 * HIN),
               make_float2(x10 * f6 + x00 * f14, x10 * f7 + x00 * f15));
    }
}

extern "C" void kernel_launch(void* const* d_in, const int* in_sizes, int n_in,
                              void* d_out, int out_size)
{
    const float* x = (const float*)d_in[0];   // (4,256,128,128)
    const float* w = (const float*)d_in[1];   // (256,256,4,4)
    float* out = (float*)d_out;               // (4,256,258,258)

    dim3 block(256);
    dim3 grid((HIN + 1 + 7) / 8, 4 * C);      // (17, 1024)
    bilinear_up_kernel<<<grid, block>>>(x, w, out);
}